// round 1
// baseline (speedup 1.0000x reference)
#include <cuda_runtime.h>

#define BB 4
#define HH 64
#define WW 64
#define LL 4096          // HH*WW
#define DM 96            // d_model
#define DI 192           // d_inner
#define DS 16            // d_state
#define DR 6             // dt_rank
#define NPROJ 38         // DR + 2*DS

// ---------------- scratch (static __device__, no allocation) ----------------
__device__ __align__(16) float  g_xcraw[BB * LL * DI];   // pre-conv x branch
__device__ __align__(16) float  g_siluz[BB * LL * DI];   // silu(z)
__device__ __align__(16) float  g_xca  [BB * LL * DI];   // conv+silu output (hw layout)
__device__ __align__(16) float2 g_dx   [BB * 2 * DI * LL]; // (delta, x) per base, d-major
__device__ __align__(16) float2 g_bc   [BB * 2 * DS * LL]; // (B, C) per base, n-major
__device__ __align__(16) float  g_ysum [BB * LL * DI];   // 4-direction accumulated y

__device__ __forceinline__ float silu_f(float v) {
    return v * __frcp_rn(1.f + __expf(-v));
}

// ---------------- kernel 1: xz = x @ W_in, split into xc / silu(z) ----------------
__global__ void k_in_gemm(const float* __restrict__ x, const float* __restrict__ Win) {
    __shared__ float xs[32][DM];     // 12 KB
    __shared__ float ws[DM][64];     // 24 KB
    const int t = threadIdx.x;       // 256
    const int row0 = blockIdx.x * 32;

    for (int i = t; i < 32 * DM; i += 256)
        xs[i / DM][i % DM] = x[(row0 + i / DM) * DM + (i % DM)];

    for (int jc = 0; jc < 6; jc++) {
        __syncthreads();
        for (int i = t; i < DM * 64; i += 256)
            ws[i / 64][i % 64] = Win[(i / 64) * 384 + jc * 64 + (i % 64)];
        __syncthreads();
        const int jl = t & 63;
        const int r0 = t >> 6;       // 0..3
        for (int rr = r0; rr < 32; rr += 4) {
            float acc = 0.f;
            #pragma unroll 8
            for (int k2 = 0; k2 < DM; k2++) acc += xs[rr][k2] * ws[k2][jl];
            const int j = jc * 64 + jl;
            const int gidx = row0 + rr;
            if (j < DI) g_xcraw[gidx * DI + j] = acc;
            else        g_siluz[gidx * DI + (j - DI)] = silu_f(acc);
        }
    }
}

// ---------------- kernel 2: depthwise 3x3 conv (SAME) + bias + SiLU ----------------
__global__ void k_conv(const float* __restrict__ cw, const float* __restrict__ cb) {
    const int idx = blockIdx.x * blockDim.x + threadIdx.x;   // over BB*LL*(DI/4)
    if (idx >= BB * LL * (DI / 4)) return;
    const int cv = idx % (DI / 4);
    const int c  = cv * 4;
    const int l  = (idx / (DI / 4)) % LL;
    const int b  = idx / (LL * (DI / 4));
    const int h = l >> 6, w = l & 63;

    float4 acc = make_float4(0.f, 0.f, 0.f, 0.f);
    #pragma unroll
    for (int kh = 0; kh < 3; kh++) {
        const int hh = h + kh - 1;
        if (hh < 0 || hh >= HH) continue;
        #pragma unroll
        for (int kw = 0; kw < 3; kw++) {
            const int wv = w + kw - 1;
            if (wv < 0 || wv >= WW) continue;
            const float4 v  = *(const float4*)&g_xcraw[((b * LL) + (hh * WW + wv)) * DI + c];
            const float4 wt = *(const float4*)&cw[(kh * 3 + kw) * DI + c];
            acc.x += v.x * wt.x; acc.y += v.y * wt.y;
            acc.z += v.z * wt.z; acc.w += v.w * wt.w;
        }
    }
    const float4 bv = *(const float4*)&cb[c];
    float4 o;
    o.x = silu_f(acc.x + bv.x);
    o.y = silu_f(acc.y + bv.y);
    o.z = silu_f(acc.z + bv.z);
    o.w = silu_f(acc.w + bv.w);
    *(float4*)&g_xca[((b * LL) + l) * DI + c] = o;
}

// ---------------- kernel 3: x-proj (dt,B,C) + delta=softplus(dt@W_dt+b) ----------------
// Writes dx (delta,x) in d-major layout and bc (B,C) in n-major layout via smem transpose.
__global__ void k_proj(const float* __restrict__ Wx, const float* __restrict__ Wdt,
                       const float* __restrict__ bdt) {
    __shared__ float rows[16][DI];       // 12 KB
    __shared__ float xdbl[16][41];       // padded, conflict-free transpose reads
    __shared__ float dsm [16][DI + 1];   // 12.4 KB
    const int t  = threadIdx.x;          // 256
    const int p0 = blockIdx.x * 16;
    const int m  = blockIdx.y;
    const int b  = blockIdx.z;

    for (int i = t; i < 16 * DI; i += 256) {
        const int pi = i / DI, c = i % DI;
        const int p = p0 + pi;
        const int src = m ? (((p & 63) << 6) | (p >> 6)) : p;   // transpose base
        rows[pi][c] = g_xca[(b * LL + src) * DI + c];
    }
    __syncthreads();

    // phase A: xdbl[pos][j] = row . W_xproj[:,j]   (16*38 dots of K=192)
    for (int i = t; i < 16 * NPROJ; i += 256) {
        const int pi = i / NPROJ, j = i % NPROJ;
        float acc = 0.f;
        #pragma unroll 8
        for (int c = 0; c < DI; c++) acc += rows[pi][c] * __ldg(&Wx[c * NPROJ + j]);
        xdbl[pi][j] = acc;
    }
    __syncthreads();

    // phase B: delta = softplus(dt @ W_dt + b_dt)
    for (int i = t; i < 16 * DI; i += 256) {
        const int pi = i / DI, d = i % DI;
        float v = __ldg(&bdt[d]);
        #pragma unroll
        for (int r = 0; r < DR; r++) v += xdbl[pi][r] * __ldg(&Wdt[r * DI + d]);
        dsm[pi][d] = (v > 20.f) ? v : log1pf(__expf(v));
    }

    // BC write (n-major, coalesced along p)
    {
        const int n  = t >> 4;      // 0..15
        const int pi = t & 15;
        g_bc[((b * 2 + m) * DS + n) * LL + p0 + pi] =
            make_float2(xdbl[pi][DR + n], xdbl[pi][DR + DS + n]);
    }
    __syncthreads();

    // dx write (d-major, coalesced along p)
    for (int i = t; i < 16 * DI; i += 256) {
        const int d = i >> 4, pi = i & 15;
        g_dx[((b * 2 + m) * DI + d) * LL + p0 + pi] =
            make_float2(dsm[pi][d], rows[pi][d]);
    }
}

// ---------------- kernel 4: zero ysum ----------------
__global__ void k_zero() {
    const int i = blockIdx.x * blockDim.x + threadIdx.x;
    if (i < BB * LL * DI / 4)
        ((float4*)g_ysum)[i] = make_float4(0.f, 0.f, 0.f, 0.f);
}

// ---------------- kernel 5: selective scan, 4 directions ----------------
// thread = (b, k, d, n); half-warp (16 lanes) = one (b,k,d) sequence.
__global__ void k_scan(const float* __restrict__ A_logs, const float* __restrict__ Ds) {
    const int t = threadIdx.x;            // 64
    const int k = blockIdx.y, b = blockIdx.z;
    const int d = blockIdx.x * 4 + (t >> 4);
    const int n = t & 15;
    const int m = k >> 1, rev = k & 1;

    const float A  = -__expf(A_logs[(k * DI + d) * DS + n]);
    const float Dv = Ds[k * DI + d];

    const float2* dxr = g_dx + (size_t)((b * 2 + m) * DI + d) * LL;
    const float2* bcr = g_bc + (size_t)((b * 2 + m) * DS + n) * LL;
    float* ys = g_ysum + (size_t)b * LL * DI + d;

    float h = 0.f;

    auto step = [&](float del, float xv, float Bv, float Cv, int p) {
        const float dA = __expf(del * A);
        h = dA * h + (del * xv) * Bv;
        float yc = h * Cv;
        yc += __shfl_xor_sync(0xffffffffu, yc, 8);
        yc += __shfl_xor_sync(0xffffffffu, yc, 4);
        yc += __shfl_xor_sync(0xffffffffu, yc, 2);
        yc += __shfl_xor_sync(0xffffffffu, yc, 1);
        if (n == 0) {
            const int tgt = m ? (((p & 63) << 6) | (p >> 6)) : p;
            atomicAdd(ys + (size_t)tgt * DI, yc + xv * Dv);
        }
    };

    if (!rev) {
        #pragma unroll 4
        for (int s = 0; s < LL; s += 2) {
            const float4 dx2 = *(const float4*)(dxr + s);
            const float4 bc2 = *(const float4*)(bcr + s);
            step(dx2.x, dx2.y, bc2.x, bc2.y, s);
            step(dx2.z, dx2.w, bc2.z, bc2.w, s + 1);
        }
    } else {
        #pragma unroll 4
        for (int s = 0; s < LL; s += 2) {
            const int pb = LL - 2 - s;
            const float4 dx2 = *(const float4*)(dxr + pb);
            const float4 bc2 = *(const float4*)(bcr + pb);
            step(dx2.z, dx2.w, bc2.z, bc2.w, pb + 1);
            step(dx2.x, dx2.y, bc2.x, bc2.y, pb);
        }
    }
}

// ---------------- kernel 6: out = (ysum * silu(z)) @ W_out ----------------
__global__ void k_out(const float* __restrict__ Wout, float* __restrict__ out) {
    __shared__ float g[32][DI];      // 24 KB
    __shared__ float ws[DI][32];     // 24 KB
    const int t = threadIdx.x;       // 256
    const int row0 = blockIdx.x * 32;

    for (int i = t; i < 32 * DI; i += 256) {
        const int r = i / DI, c = i % DI;
        const int gi = (row0 + r) * DI + c;
        g[r][c] = g_ysum[gi] * g_siluz[gi];
    }

    for (int jc = 0; jc < 3; jc++) {
        __syncthreads();
        for (int i = t; i < DI * 32; i += 256)
            ws[i / 32][i % 32] = Wout[(i / 32) * DM + jc * 32 + (i % 32)];
        __syncthreads();
        const int jl = t & 31;
        const int r0 = t >> 5;       // 0..7
        for (int rr = r0; rr < 32; rr += 8) {
            float acc = 0.f;
            #pragma unroll 8
            for (int k2 = 0; k2 < DI; k2++) acc += g[rr][k2] * ws[k2][jl];
            out[(row0 + rr) * DM + jc * 32 + jl] = acc;
        }
    }
}

// ---------------- launch ----------------
extern "C" void kernel_launch(void* const* d_in, const int* in_sizes, int n_in,
                              void* d_out, int out_size) {
    const float* x     = (const float*)d_in[0];
    const float* Win   = (const float*)d_in[1];
    const float* cw    = (const float*)d_in[2];
    const float* cb    = (const float*)d_in[3];
    const float* Wx    = (const float*)d_in[4];
    const float* Wdt   = (const float*)d_in[5];
    const float* bdt   = (const float*)d_in[6];
    const float* Alogs = (const float*)d_in[7];
    const float* Ds    = (const float*)d_in[8];
    const float* Wout  = (const float*)d_in[9];
    float* out = (float*)d_out;

    k_in_gemm<<<(BB * LL) / 32, 256>>>(x, Win);
    k_conv<<<(BB * LL * (DI / 4) + 255) / 256, 256>>>(cw, cb);
    dim3 gp(LL / 16, 2, BB);
    k_proj<<<gp, 256>>>(Wx, Wdt, bdt);
    k_zero<<<(BB * LL * DI / 4 + 255) / 256, 256>>>();
    dim3 gs(DI / 4, 4, BB);
    k_scan<<<gs, 64>>>(Alogs, Ds);
    k_out<<<(BB * LL) / 32, 256>>>(Wout, out);
}

// round 2
// speedup vs baseline: 1.8023x; 1.8023x over previous
#include <cuda_runtime.h>

#define BB 4
#define HH 64
#define WW 64
#define LL 4096          // HH*WW
#define DM 96
#define DI 192
#define DS 16
#define DR 6
#define NPROJ 38

// ---------------- scratch ----------------
__device__ __align__(16) float  g_xcraw[BB * LL * DI];
__device__ __align__(16) float  g_siluz[BB * LL * DI];
__device__ __align__(16) float  g_xca  [BB * LL * DI];
__device__ __align__(16) float2 g_dx   [BB * 2 * DI * LL];   // (delta,x) d-major
__device__ __align__(16) float4 g_bc4  [BB * 2 * LL * 8];    // per pos: 8x (Bj,Cj,Bj+8,Cj+8)
__device__ __align__(16) float  g_ysum [BB * LL * DI];

__device__ __forceinline__ float silu_f(float v) {
    return v * __frcp_rn(1.f + __expf(-v));
}
__device__ __forceinline__ float ex2f(float x) {
    float y; asm("ex2.approx.ftz.f32 %0, %1;" : "=f"(y) : "f"(x)); return y;
}

// ---------------- kernel 0: zero ysum ----------------
__global__ void k_zero() {
    const int i = blockIdx.x * blockDim.x + threadIdx.x;
    if (i < BB * LL * DI / 4)
        ((float4*)g_ysum)[i] = make_float4(0.f, 0.f, 0.f, 0.f);
}

// ---------------- kernel 1: xz = x @ W_in (64x64 tile, 4x4 microtile) ----------------
__global__ void k_in_gemm(const float* __restrict__ x, const float* __restrict__ Win) {
    __shared__ __align__(16) float xs[64][96];   // 24 KB  (row-major, K inner)
    __shared__ __align__(16) float ws[96][64];   // 24 KB
    const int t = threadIdx.x;                   // 256
    const int row0 = blockIdx.x * 64;
    const int col0 = blockIdx.y * 64;

    {   // x tile: 64*96 floats = 1536 float4
        const float4* xg = (const float4*)(x + (size_t)row0 * DM);
        float4* xv = (float4*)&xs[0][0];
        #pragma unroll
        for (int i = 0; i < 6; i++) xv[t + i * 256] = xg[t + i * 256];
    }
    {   // W tile: 96*64 = 1536 float4? no: 96*16 float4 per.. 96*64/4 = 1536
        #pragma unroll
        for (int i = 0; i < 6; i++) {
            const int idx = t + i * 256;
            const int k = idx >> 4, c4 = idx & 15;
            *(float4*)&ws[k][c4 * 4] = *(const float4*)&Win[k * (2 * DI) + col0 + c4 * 4];
        }
    }
    __syncthreads();

    const int tx = t & 15, ty = t >> 4;
    float acc[4][4];
    #pragma unroll
    for (int i = 0; i < 4; i++)
        #pragma unroll
        for (int jj = 0; jj < 4; jj++) acc[i][jj] = 0.f;

    #pragma unroll 8
    for (int kk = 0; kk < 96; kk++) {
        const float4 bv = *(const float4*)&ws[kk][tx * 4];
        const float a0 = xs[ty * 4 + 0][kk];
        const float a1 = xs[ty * 4 + 1][kk];
        const float a2 = xs[ty * 4 + 2][kk];
        const float a3 = xs[ty * 4 + 3][kk];
        acc[0][0] += a0 * bv.x; acc[0][1] += a0 * bv.y; acc[0][2] += a0 * bv.z; acc[0][3] += a0 * bv.w;
        acc[1][0] += a1 * bv.x; acc[1][1] += a1 * bv.y; acc[1][2] += a1 * bv.z; acc[1][3] += a1 * bv.w;
        acc[2][0] += a2 * bv.x; acc[2][1] += a2 * bv.y; acc[2][2] += a2 * bv.z; acc[2][3] += a2 * bv.w;
        acc[3][0] += a3 * bv.x; acc[3][1] += a3 * bv.y; acc[3][2] += a3 * bv.z; acc[3][3] += a3 * bv.w;
    }

    if (col0 < DI) {
        #pragma unroll
        for (int i = 0; i < 4; i++) {
            const int row = row0 + ty * 4 + i;
            *(float4*)&g_xcraw[(size_t)row * DI + col0 + tx * 4] =
                make_float4(acc[i][0], acc[i][1], acc[i][2], acc[i][3]);
        }
    } else {
        const int c = col0 - DI;
        #pragma unroll
        for (int i = 0; i < 4; i++) {
            const int row = row0 + ty * 4 + i;
            *(float4*)&g_siluz[(size_t)row * DI + c + tx * 4] =
                make_float4(silu_f(acc[i][0]), silu_f(acc[i][1]),
                            silu_f(acc[i][2]), silu_f(acc[i][3]));
        }
    }
}

// ---------------- kernel 2: depthwise 3x3 conv + bias + SiLU ----------------
__global__ void k_conv(const float* __restrict__ cw, const float* __restrict__ cb) {
    const int idx = blockIdx.x * blockDim.x + threadIdx.x;
    if (idx >= BB * LL * (DI / 4)) return;
    const int cv = idx % (DI / 4);
    const int c  = cv * 4;
    const int l  = (idx / (DI / 4)) % LL;
    const int b  = idx / (LL * (DI / 4));
    const int h = l >> 6, w = l & 63;

    float4 acc = make_float4(0.f, 0.f, 0.f, 0.f);
    #pragma unroll
    for (int kh = 0; kh < 3; kh++) {
        const int hh = h + kh - 1;
        if (hh < 0 || hh >= HH) continue;
        #pragma unroll
        for (int kw = 0; kw < 3; kw++) {
            const int wv = w + kw - 1;
            if (wv < 0 || wv >= WW) continue;
            const float4 v  = *(const float4*)&g_xcraw[((size_t)(b * LL) + (hh * WW + wv)) * DI + c];
            const float4 wt = *(const float4*)&cw[(kh * 3 + kw) * DI + c];
            acc.x += v.x * wt.x; acc.y += v.y * wt.y;
            acc.z += v.z * wt.z; acc.w += v.w * wt.w;
        }
    }
    const float4 bv = *(const float4*)&cb[c];
    float4 o;
    o.x = silu_f(acc.x + bv.x);
    o.y = silu_f(acc.y + bv.y);
    o.z = silu_f(acc.z + bv.z);
    o.w = silu_f(acc.w + bv.w);
    *(float4*)&g_xca[((size_t)(b * LL) + l) * DI + c] = o;
}

// ---------------- kernel 3: x-proj + delta, write dx/bc ----------------
__global__ void k_proj(const float* __restrict__ Wx, const float* __restrict__ Wdt,
                       const float* __restrict__ bdt) {
    __shared__ float rows[16][DI];            // 12 KB
    __shared__ float Wxs[DI][NPROJ];          // 29.2 KB
    __shared__ float xdbl[16][40];
    const int t  = threadIdx.x;               // 256
    const int p0 = blockIdx.x * 16;
    const int m  = blockIdx.y;
    const int b  = blockIdx.z;

    for (int i = t; i < 16 * DI; i += 256) {
        const int pi = i / DI, c = i % DI;
        const int p = p0 + pi;
        const int src = m ? (((p & 63) << 6) | (p >> 6)) : p;
        rows[pi][c] = g_xca[((size_t)b * LL + src) * DI + c];
    }
    for (int i = t; i < DI * NPROJ; i += 256) ((float*)Wxs)[i] = Wx[i];
    __syncthreads();

    for (int i = t; i < 16 * NPROJ; i += 256) {
        const int pi = i / NPROJ, j = i % NPROJ;
        float acc = 0.f;
        #pragma unroll 8
        for (int c = 0; c < DI; c++) acc += rows[pi][c] * Wxs[c][j];
        xdbl[pi][j] = acc;
    }
    __syncthreads();

    // bc write: packed (Bj,Cj | Bj+8,Cj+8) position-major
    {
        const int pi = t >> 4, n = t & 15;
        ((float2*)g_bc4)[(((size_t)(b * 2 + m) * LL + p0 + pi) * 8 + (n & 7)) * 2 + (n >> 3)] =
            make_float2(xdbl[pi][DR + n], xdbl[pi][DR + DS + n]);
    }

    // delta + dx write (d-major, p-coalesced)
    for (int i = t; i < 16 * DI; i += 256) {
        const int d = i >> 4, pi = i & 15;
        float v = __ldg(&bdt[d]);
        #pragma unroll
        for (int r = 0; r < DR; r++) v += xdbl[pi][r] * __ldg(&Wdt[r * DI + d]);
        const float sp = (v > 20.f) ? v : log1pf(__expf(v));
        g_dx[((size_t)((b * 2 + m) * DI + d)) * LL + p0 + pi] = make_float2(sp, rows[pi][d]);
    }
}

// ---------------- kernel 4: selective scan ----------------
// warp covers 4 d; lane = dl*8 + j; thread owns states n=j and n=j+8.
#define LOADB(s, dA_, dB_, c0_, c1_, c2_, c3_)                         \
    dA_ = *(const float4*)(dxr + (s));                                 \
    dB_ = *(const float4*)(dxr + (s) + 2);                             \
    c0_ = bcr[(size_t)((s) + 0) * 8];                                  \
    c1_ = bcr[(size_t)((s) + 1) * 8];                                  \
    c2_ = bcr[(size_t)((s) + 2) * 8];                                  \
    c3_ = bcr[(size_t)((s) + 3) * 8];

#define STEP(del, xv, bc, p) {                                         \
    const float dA0 = ex2f((del) * A0);                                \
    const float dA1 = ex2f((del) * A1);                                \
    const float tv = (del) * (xv);                                     \
    h0 = fmaf(dA0, h0, tv * (bc).x);                                   \
    h1 = fmaf(dA1, h1, tv * (bc).z);                                   \
    float y = fmaf(h1, (bc).w, h0 * (bc).y);                           \
    y += __shfl_xor_sync(0xffffffffu, y, 1);                           \
    y += __shfl_xor_sync(0xffffffffu, y, 2);                           \
    y += __shfl_xor_sync(0xffffffffu, y, 4);                           \
    if (j == 0) {                                                      \
        const int pp = (p);                                            \
        const int tgt = m ? (((pp & 63) << 6) | (pp >> 6)) : pp;       \
        atomicAdd(ys + (size_t)tgt * DI, y + (xv) * Dv);               \
    } }

__global__ void k_scan(const float* __restrict__ A_logs, const float* __restrict__ Ds) {
    const int t = threadIdx.x;            // 32
    const int k = blockIdx.y, b = blockIdx.z;
    const int d = blockIdx.x * 4 + (t >> 3);
    const int j = t & 7;
    const int m = k >> 1, rev = k & 1;
    const float L2E = 1.4426950408889634f;

    const float A0 = -__expf(A_logs[(k * DI + d) * DS + j])     * L2E;
    const float A1 = -__expf(A_logs[(k * DI + d) * DS + j + 8]) * L2E;
    const float Dv = Ds[k * DI + d];

    const float2* dxr = g_dx  + (size_t)((b * 2 + m) * DI + d) * LL;
    const float4* bcr = g_bc4 + (size_t)(b * 2 + m) * LL * 8 + j;
    float* ys = g_ysum + (size_t)b * LL * DI + d;

    float h0 = 0.f, h1 = 0.f;

    if (!rev) {
        float4 aA, aB, a0, a1, a2, a3;
        float4 bA, bB, b0, b1, b2, b3;
        LOADB(0, aA, aB, a0, a1, a2, a3);
        LOADB(4, bA, bB, b0, b1, b2, b3);
        for (int s = 0; s < LL; s += 4) {
            float4 cA, cB, c0, c1, c2, c3;
            const int pf = (s + 8 < LL) ? s + 8 : 0;
            LOADB(pf, cA, cB, c0, c1, c2, c3);
            STEP(aA.x, aA.y, a0, s);
            STEP(aA.z, aA.w, a1, s + 1);
            STEP(aB.x, aB.y, a2, s + 2);
            STEP(aB.z, aB.w, a3, s + 3);
            aA = bA; aB = bB; a0 = b0; a1 = b1; a2 = b2; a3 = b3;
            bA = cA; bB = cB; b0 = c0; b1 = c1; b2 = c2; b3 = c3;
        }
    } else {
        float4 aA, aB, a0, a1, a2, a3;
        float4 bA, bB, b0, b1, b2, b3;
        LOADB(LL - 4, aA, aB, a0, a1, a2, a3);
        LOADB(LL - 8, bA, bB, b0, b1, b2, b3);
        for (int s = LL - 4; s >= 0; s -= 4) {
            float4 cA, cB, c0, c1, c2, c3;
            const int pf = (s - 8 >= 0) ? s - 8 : 0;
            LOADB(pf, cA, cB, c0, c1, c2, c3);
            STEP(aB.z, aB.w, a3, s + 3);
            STEP(aB.x, aB.y, a2, s + 2);
            STEP(aA.z, aA.w, a1, s + 1);
            STEP(aA.x, aA.y, a0, s);
            aA = bA; aB = bB; a0 = b0; a1 = b1; a2 = b2; a3 = b3;
            bA = cA; bB = cB; b0 = c0; b1 = c1; b2 = c2; b3 = c3;
        }
    }
}

// ---------------- kernel 5: out = (ysum * siluz) @ W_out ----------------
__global__ void k_out(const float* __restrict__ Wout, float* __restrict__ out) {
    __shared__ __align__(16) float ins[64][96];   // 24 KB
    __shared__ __align__(16) float ws[96][32];    // 12 KB
    const int t = threadIdx.x;                    // 128
    const int row0 = blockIdx.x * 64;
    const int col0 = blockIdx.y * 32;
    const int tx = t & 7, ty = t >> 3;

    float acc[4][4];
    #pragma unroll
    for (int i = 0; i < 4; i++)
        #pragma unroll
        for (int jj = 0; jj < 4; jj++) acc[i][jj] = 0.f;

    for (int kc = 0; kc < 2; kc++) {
        __syncthreads();
        #pragma unroll
        for (int i = 0; i < 12; i++) {          // 64*24 float4
            const int idx = t + i * 128;
            const int r = idx / 24, k4 = idx % 24;
            const size_t gi = (size_t)(row0 + r) * DI + kc * 96 + k4 * 4;
            const float4 a = *(const float4*)&g_ysum[gi];
            const float4 z = *(const float4*)&g_siluz[gi];
            *(float4*)&ins[r][k4 * 4] = make_float4(a.x * z.x, a.y * z.y, a.z * z.z, a.w * z.w);
        }
        #pragma unroll
        for (int i = 0; i < 6; i++) {           // 96*8 float4
            const int idx = t + i * 128;
            const int kk = idx / 8, c4 = idx % 8;
            *(float4*)&ws[kk][c4 * 4] = *(const float4*)&Wout[(kc * 96 + kk) * DM + col0 + c4 * 4];
        }
        __syncthreads();

        #pragma unroll 8
        for (int kk = 0; kk < 96; kk++) {
            const float4 bv = *(const float4*)&ws[kk][tx * 4];
            const float a0 = ins[ty * 4 + 0][kk];
            const float a1 = ins[ty * 4 + 1][kk];
            const float a2 = ins[ty * 4 + 2][kk];
            const float a3 = ins[ty * 4 + 3][kk];
            acc[0][0] += a0 * bv.x; acc[0][1] += a0 * bv.y; acc[0][2] += a0 * bv.z; acc[0][3] += a0 * bv.w;
            acc[1][0] += a1 * bv.x; acc[1][1] += a1 * bv.y; acc[1][2] += a1 * bv.z; acc[1][3] += a1 * bv.w;
            acc[2][0] += a2 * bv.x; acc[2][1] += a2 * bv.y; acc[2][2] += a2 * bv.z; acc[2][3] += a2 * bv.w;
            acc[3][0] += a3 * bv.x; acc[3][1] += a3 * bv.y; acc[3][2] += a3 * bv.z; acc[3][3] += a3 * bv.w;
        }
    }

    #pragma unroll
    for (int i = 0; i < 4; i++) {
        const int row = row0 + ty * 4 + i;
        *(float4*)&out[(size_t)row * DM + col0 + tx * 4] =
            make_float4(acc[i][0], acc[i][1], acc[i][2], acc[i][3]);
    }
}

// ---------------- launch ----------------
extern "C" void kernel_launch(void* const* d_in, const int* in_sizes, int n_in,
                              void* d_out, int out_size) {
    const float* x     = (const float*)d_in[0];
    const float* Win   = (const float*)d_in[1];
    const float* cw    = (const float*)d_in[2];
    const float* cb    = (const float*)d_in[3];
    const float* Wx    = (const float*)d_in[4];
    const float* Wdt   = (const float*)d_in[5];
    const float* bdt   = (const float*)d_in[6];
    const float* Alogs = (const float*)d_in[7];
    const float* Ds    = (const float*)d_in[8];
    const float* Wout  = (const float*)d_in[9];
    float* out = (float*)d_out;

    k_zero<<<(BB * LL * DI / 4 + 255) / 256, 256>>>();
    dim3 gg(BB * LL / 64, 6);
    k_in_gemm<<<gg, 256>>>(x, Win);
    k_conv<<<(BB * LL * (DI / 4) + 255) / 256, 256>>>(cw, cb);
    dim3 gp(LL / 16, 2, BB);
    k_proj<<<gp, 256>>>(Wx, Wdt, bdt);
    dim3 gs(DI / 4, 4, BB);
    k_scan<<<gs, 32>>>(Alogs, Ds);
    dim3 go(BB * LL / 64, 3);
    k_out<<<go, 128>>>(Wout, out);
}

// round 4
// speedup vs baseline: 2.1346x; 1.1844x over previous
#include <cuda_runtime.h>

#define BB 4
#define HH 64
#define WW 64
#define LL 4096
#define DM 96
#define DI 192
#define DS 16
#define DR 6
#define NPROJ 38

// ---------------- scratch ----------------
__device__ __align__(16) float  g_xcraw[BB * LL * DI];
__device__ __align__(16) float  g_siluz[BB * LL * DI];
__device__ __align__(16) float  g_xca  [BB * LL * DI];
__device__ __align__(16) float2 g_dx   [BB * 2 * DI * LL];   // (delta,x) d-major
__device__ __align__(16) float4 g_bc4  [BB * 2 * LL * 8];    // per pos: 8x (Bj,Cj,Bj+8,Cj+8)
__device__ __align__(16) float  g_ysum [BB * LL * DI];

__device__ __forceinline__ float silu_f(float v) {
    return v * __frcp_rn(1.f + __expf(-v));
}
__device__ __forceinline__ float ex2f(float x) {
    float y; asm("ex2.approx.ftz.f32 %0, %1;" : "=f"(y) : "f"(x)); return y;
}

// ---------------- kernel 1: xz = x @ W_in (64x64 tile, 4x4 microtile) ----------------
__global__ void k_in_gemm(const float* __restrict__ x, const float* __restrict__ Win) {
    __shared__ __align__(16) float xs[64][96];
    __shared__ __align__(16) float ws[96][64];
    const int t = threadIdx.x;                   // 256
    const int row0 = blockIdx.x * 64;
    const int col0 = blockIdx.y * 64;

    {
        const float4* xg = (const float4*)(x + (size_t)row0 * DM);
        float4* xv = (float4*)&xs[0][0];
        #pragma unroll
        for (int i = 0; i < 6; i++) xv[t + i * 256] = xg[t + i * 256];
    }
    {
        #pragma unroll
        for (int i = 0; i < 6; i++) {
            const int idx = t + i * 256;
            const int k = idx >> 4, c4 = idx & 15;
            *(float4*)&ws[k][c4 * 4] = *(const float4*)&Win[k * (2 * DI) + col0 + c4 * 4];
        }
    }
    __syncthreads();

    const int tx = t & 15, ty = t >> 4;
    float acc[4][4];
    #pragma unroll
    for (int i = 0; i < 4; i++)
        #pragma unroll
        for (int jj = 0; jj < 4; jj++) acc[i][jj] = 0.f;

    #pragma unroll 8
    for (int kk = 0; kk < 96; kk++) {
        const float4 bv = *(const float4*)&ws[kk][tx * 4];
        const float a0 = xs[ty * 4 + 0][kk];
        const float a1 = xs[ty * 4 + 1][kk];
        const float a2 = xs[ty * 4 + 2][kk];
        const float a3 = xs[ty * 4 + 3][kk];
        acc[0][0] += a0 * bv.x; acc[0][1] += a0 * bv.y; acc[0][2] += a0 * bv.z; acc[0][3] += a0 * bv.w;
        acc[1][0] += a1 * bv.x; acc[1][1] += a1 * bv.y; acc[1][2] += a1 * bv.z; acc[1][3] += a1 * bv.w;
        acc[2][0] += a2 * bv.x; acc[2][1] += a2 * bv.y; acc[2][2] += a2 * bv.z; acc[2][3] += a2 * bv.w;
        acc[3][0] += a3 * bv.x; acc[3][1] += a3 * bv.y; acc[3][2] += a3 * bv.z; acc[3][3] += a3 * bv.w;
    }

    if (col0 < DI) {
        #pragma unroll
        for (int i = 0; i < 4; i++) {
            const int row = row0 + ty * 4 + i;
            *(float4*)&g_xcraw[(size_t)row * DI + col0 + tx * 4] =
                make_float4(acc[i][0], acc[i][1], acc[i][2], acc[i][3]);
        }
    } else {
        const int c = col0 - DI;
        #pragma unroll
        for (int i = 0; i < 4; i++) {
            const int row = row0 + ty * 4 + i;
            *(float4*)&g_siluz[(size_t)row * DI + c + tx * 4] =
                make_float4(silu_f(acc[i][0]), silu_f(acc[i][1]),
                            silu_f(acc[i][2]), silu_f(acc[i][3]));
        }
    }
}

// ---------------- kernel 2: depthwise 3x3 conv + bias + SiLU ----------------
__global__ void k_conv(const float* __restrict__ cw, const float* __restrict__ cb) {
    const int idx = blockIdx.x * blockDim.x + threadIdx.x;
    if (idx >= BB * LL * (DI / 4)) return;
    const int cv = idx % (DI / 4);
    const int c  = cv * 4;
    const int l  = (idx / (DI / 4)) % LL;
    const int b  = idx / (LL * (DI / 4));
    const int h = l >> 6, w = l & 63;

    float4 acc = make_float4(0.f, 0.f, 0.f, 0.f);
    #pragma unroll
    for (int kh = 0; kh < 3; kh++) {
        const int hh = h + kh - 1;
        if (hh < 0 || hh >= HH) continue;
        #pragma unroll
        for (int kw = 0; kw < 3; kw++) {
            const int wv = w + kw - 1;
            if (wv < 0 || wv >= WW) continue;
            const float4 v  = *(const float4*)&g_xcraw[((size_t)(b * LL) + (hh * WW + wv)) * DI + c];
            const float4 wt = *(const float4*)&cw[(kh * 3 + kw) * DI + c];
            acc.x += v.x * wt.x; acc.y += v.y * wt.y;
            acc.z += v.z * wt.z; acc.w += v.w * wt.w;
        }
    }
    const float4 bv = *(const float4*)&cb[c];
    float4 o;
    o.x = silu_f(acc.x + bv.x);
    o.y = silu_f(acc.y + bv.y);
    o.z = silu_f(acc.z + bv.z);
    o.w = silu_f(acc.w + bv.w);
    *(float4*)&g_xca[((size_t)(b * LL) + l) * DI + c] = o;
}

// ---------------- kernel 3: x-proj + delta + zero ysum (register-tiled) ----------------
// block: 64 positions, one (b,m). 160 threads, 4x4 microtile over 64x40.
__global__ __launch_bounds__(160) void k_proj(const float* __restrict__ Wx,
                                              const float* __restrict__ Wdt,
                                              const float* __restrict__ bdt) {
    __shared__ __align__(16) float xs[64][33];    // K/d tile, padded
    __shared__ __align__(16) float ws[32][40];    // Wx K-tile, cols padded to 40
    __shared__ float xdbl[64][41];                // projection result, padded
    const int t  = threadIdx.x;                   // 160
    const int p0 = blockIdx.x * 64;
    const int m  = blockIdx.y;
    const int b  = blockIdx.z;
    const int tx = t % 10, ty = t / 10;

    // zero ysum rows (m=0 blocks only; contiguous region)
    if (m == 0) {
        float4* yz = (float4*)&g_ysum[((size_t)b * LL + p0) * DI];
        for (int i = t; i < 64 * DI / 4; i += 160)
            yz[i] = make_float4(0.f, 0.f, 0.f, 0.f);
    }

    float acc[4][4];
    #pragma unroll
    for (int i = 0; i < 4; i++)
        #pragma unroll
        for (int q = 0; q < 4; q++) acc[i][q] = 0.f;

    // phase A: xdbl[64][38] = rows[64][192] @ Wx[192][38], K-tiled by 32
    for (int kt = 0; kt < 6; kt++) {
        __syncthreads();
        for (int i = t; i < 64 * 32; i += 160) {
            const int r = i >> 5, c = i & 31;
            const int p = p0 + r;
            const int src = m ? (((p & 63) << 6) | (p >> 6)) : p;
            xs[r][c] = g_xca[((size_t)b * LL + src) * DI + kt * 32 + c];
        }
        for (int i = t; i < 32 * 40; i += 160) {
            const int k = i / 40, j = i % 40;
            ws[k][j] = (j < NPROJ) ? Wx[(kt * 32 + k) * NPROJ + j] : 0.f;
        }
        __syncthreads();

        #pragma unroll 8
        for (int kk = 0; kk < 32; kk++) {
            const float4 bv = *(const float4*)&ws[kk][tx * 4];
            const float a0 = xs[ty * 4 + 0][kk];
            const float a1 = xs[ty * 4 + 1][kk];
            const float a2 = xs[ty * 4 + 2][kk];
            const float a3 = xs[ty * 4 + 3][kk];
            acc[0][0] += a0 * bv.x; acc[0][1] += a0 * bv.y; acc[0][2] += a0 * bv.z; acc[0][3] += a0 * bv.w;
            acc[1][0] += a1 * bv.x; acc[1][1] += a1 * bv.y; acc[1][2] += a1 * bv.z; acc[1][3] += a1 * bv.w;
            acc[2][0] += a2 * bv.x; acc[2][1] += a2 * bv.y; acc[2][2] += a2 * bv.z; acc[2][3] += a2 * bv.w;
            acc[3][0] += a3 * bv.x; acc[3][1] += a3 * bv.y; acc[3][2] += a3 * bv.z; acc[3][3] += a3 * bv.w;
        }
    }
    #pragma unroll
    for (int i = 0; i < 4; i++)
        #pragma unroll
        for (int q = 0; q < 4; q++)
            xdbl[ty * 4 + i][tx * 4 + q] = acc[i][q];
    __syncthreads();

    // BC write: packed (Bj,Cj | Bj+8,Cj+8), position-major, p-coalesced per pos
    for (int i = t; i < 64 * 16; i += 160) {
        const int pi = i >> 4, n = i & 15;
        ((float2*)g_bc4)[(((size_t)(b * 2 + m) * LL + p0 + pi) * 8 + (n & 7)) * 2 + (n >> 3)] =
            make_float2(xdbl[pi][DR + n], xdbl[pi][DR + DS + n]);
    }

    // phase B: delta + dx write, d-tiled by 32 (reload x tile for coalesced access)
    for (int dt = 0; dt < 6; dt++) {
        __syncthreads();
        for (int i = t; i < 64 * 32; i += 160) {
            const int r = i >> 5, c = i & 31;
            const int p = p0 + r;
            const int src = m ? (((p & 63) << 6) | (p >> 6)) : p;
            xs[r][c] = g_xca[((size_t)b * LL + src) * DI + dt * 32 + c];
        }
        __syncthreads();
        for (int i = t; i < 32 * 64; i += 160) {
            const int dl = i >> 6, pi = i & 63;
            const int d = dt * 32 + dl;
            float v = __ldg(&bdt[d]);
            #pragma unroll
            for (int r = 0; r < DR; r++) v += xdbl[pi][r] * __ldg(&Wdt[r * DI + d]);
            const float sp = (v > 20.f) ? v : log1pf(__expf(v));
            g_dx[((size_t)((b * 2 + m) * DI + d)) * LL + p0 + pi] =
                make_float2(sp, xs[pi][dl]);
        }
    }
}

// ---------------- kernel 4: selective scan (2-chunk, 3-deep prefetch) ----------------
struct St { float4 dA_, dB_, c0, c1, c2, c3; };

#define LOADS(dst, s)                                                  \
    dst.dA_ = *(const float4*)(dxr + (s));                             \
    dst.dB_ = *(const float4*)(dxr + (s) + 2);                         \
    dst.c0 = bcr[(size_t)((s) + 0) * 8];                               \
    dst.c1 = bcr[(size_t)((s) + 1) * 8];                               \
    dst.c2 = bcr[(size_t)((s) + 2) * 8];                               \
    dst.c3 = bcr[(size_t)((s) + 3) * 8];

#define STEPX(del, xv, bc, p, EMIT) {                                  \
    const float dA0 = ex2f((del) * A0);                                \
    const float dA1 = ex2f((del) * A1);                                \
    const float tv = (del) * (xv);                                     \
    h0 = fmaf(dA0, h0, tv * (bc).x);                                   \
    h1 = fmaf(dA1, h1, tv * (bc).z);                                   \
    if (EMIT) {                                                        \
        float y = fmaf(h1, (bc).w, h0 * (bc).y);                       \
        y += __shfl_xor_sync(0xffffffffu, y, 1);                       \
        y += __shfl_xor_sync(0xffffffffu, y, 2);                       \
        y += __shfl_xor_sync(0xffffffffu, y, 4);                       \
        if (j == 0) {                                                  \
            const int pp = (p);                                        \
            const int tgt = m ? (((pp & 63) << 6) | (pp >> 6)) : pp;   \
            atomicAdd(ys + (size_t)tgt * DI, y + (xv) * Dv);           \
        }                                                              \
    } }

#define WALK(REV, EMIT, lo, hi) {                                      \
    St a, bb_, cc_;                                                    \
    if (!(REV)) {                                                      \
        LOADS(a, (lo)); LOADS(bb_, (lo) + 4); LOADS(cc_, (lo) + 8);    \
        for (int s = (lo); s < (hi); s += 4) {                         \
            St dd_;                                                    \
            const int pf = (s + 12 < (hi)) ? s + 12 : (lo);            \
            LOADS(dd_, pf);                                            \
            STEPX(a.dA_.x, a.dA_.y, a.c0, s, EMIT);                    \
            STEPX(a.dA_.z, a.dA_.w, a.c1, s + 1, EMIT);                \
            STEPX(a.dB_.x, a.dB_.y, a.c2, s + 2, EMIT);                \
            STEPX(a.dB_.z, a.dB_.w, a.c3, s + 3, EMIT);                \
            a = bb_; bb_ = cc_; cc_ = dd_;                             \
        }                                                              \
    } else {                                                           \
        LOADS(a, (hi) - 4); LOADS(bb_, (hi) - 8); LOADS(cc_, (hi) - 12); \
        for (int s = (hi) - 4; s >= (lo); s -= 4) {                    \
            St dd_;                                                    \
            const int pf = (s - 12 >= (lo)) ? s - 12 : (lo);           \
            LOADS(dd_, pf);                                            \
            STEPX(a.dB_.z, a.dB_.w, a.c3, s + 3, EMIT);                \
            STEPX(a.dB_.x, a.dB_.y, a.c2, s + 2, EMIT);                \
            STEPX(a.dA_.z, a.dA_.w, a.c1, s + 1, EMIT);                \
            STEPX(a.dA_.x, a.dA_.y, a.c0, s, EMIT);                    \
            a = bb_; bb_ = cc_; cc_ = dd_;                             \
        }                                                              \
    } }

__global__ __launch_bounds__(32) void k_scan(const float* __restrict__ A_logs,
                                             const float* __restrict__ Ds) {
    const int t = threadIdx.x;                 // 32
    const int k = blockIdx.y >> 1;             // direction 0..3
    const int ch = blockIdx.y & 1;             // chunk 0/1 (in scan order)
    const int b = blockIdx.z;
    const int d = blockIdx.x * 4 + (t >> 3);
    const int j = t & 7;
    const int m = k >> 1, rev = k & 1;
    const float L2E = 1.4426950408889634f;
    const int HALF = LL / 2;

    const float A0 = -__expf(A_logs[(k * DI + d) * DS + j])     * L2E;
    const float A1 = -__expf(A_logs[(k * DI + d) * DS + j + 8]) * L2E;
    const float Dv = Ds[k * DI + d];

    const float2* dxr = g_dx  + (size_t)((b * 2 + m) * DI + d) * LL;
    const float4* bcr = g_bc4 + (size_t)(b * 2 + m) * LL * 8 + j;
    float* ys = g_ysum + (size_t)b * LL * DI + d;

    float h0 = 0.f, h1 = 0.f;

    if (!rev) {
        if (ch == 0) {
            WALK(0, 1, 0, HALF);
        } else {
            WALK(0, 0, 0, HALF);        // state-only replay
            WALK(0, 1, HALF, LL);
        }
    } else {
        if (ch == 0) {
            WALK(1, 1, HALF, LL);
        } else {
            WALK(1, 0, HALF, LL);       // state-only replay
            WALK(1, 1, 0, HALF);
        }
    }
}

// ---------------- kernel 5: out = (ysum * siluz) @ W_out ----------------
__global__ void k_out(const float* __restrict__ Wout, float* __restrict__ out) {
    __shared__ __align__(16) float ins[64][96];
    __shared__ __align__(16) float ws[96][32];
    const int t = threadIdx.x;                    // 128
    const int row0 = blockIdx.x * 64;
    const int col0 = blockIdx.y * 32;
    const int tx = t & 7, ty = t >> 3;

    float acc[4][4];
    #pragma unroll
    for (int i = 0; i < 4; i++)
        #pragma unroll
        for (int jj = 0; jj < 4; jj++) acc[i][jj] = 0.f;

    for (int kc = 0; kc < 2; kc++) {
        __syncthreads();
        #pragma unroll
        for (int i = 0; i < 12; i++) {
            const int idx = t + i * 128;
            const int r = idx / 24, k4 = idx % 24;
            const size_t gi = (size_t)(row0 + r) * DI + kc * 96 + k4 * 4;
            const float4 a = *(const float4*)&g_ysum[gi];
            const float4 z = *(const float4*)&g_siluz[gi];
            *(float4*)&ins[r][k4 * 4] = make_float4(a.x * z.x, a.y * z.y, a.z * z.z, a.w * z.w);
        }
        #pragma unroll
        for (int i = 0; i < 6; i++) {
            const int idx = t + i * 128;
            const int kk = idx / 8, c4 = idx % 8;
            *(float4*)&ws[kk][c4 * 4] = *(const float4*)&Wout[(kc * 96 + kk) * DM + col0 + c4 * 4];
        }
        __syncthreads();

        #pragma unroll 8
        for (int kk = 0; kk < 96; kk++) {
            const float4 bv = *(const float4*)&ws[kk][tx * 4];
            const float a0 = ins[ty * 4 + 0][kk];
            const float a1 = ins[ty * 4 + 1][kk];
            const float a2 = ins[ty * 4 + 2][kk];
            const float a3 = ins[ty * 4 + 3][kk];
            acc[0][0] += a0 * bv.x; acc[0][1] += a0 * bv.y; acc[0][2] += a0 * bv.z; acc[0][3] += a0 * bv.w;
            acc[1][0] += a1 * bv.x; acc[1][1] += a1 * bv.y; acc[1][2] += a1 * bv.z; acc[1][3] += a1 * bv.w;
            acc[2][0] += a2 * bv.x; acc[2][1] += a2 * bv.y; acc[2][2] += a2 * bv.z; acc[2][3] += a2 * bv.w;
            acc[3][0] += a3 * bv.x; acc[3][1] += a3 * bv.y; acc[3][2] += a3 * bv.z; acc[3][3] += a3 * bv.w;
        }
    }

    #pragma unroll
    for (int i = 0; i < 4; i++) {
        const int row = row0 + ty * 4 + i;
        *(float4*)&out[(size_t)row * DM + col0 + tx * 4] =
            make_float4(acc[i][0], acc[i][1], acc[i][2], acc[i][3]);
    }
}

// ---------------- launch ----------------
extern "C" void kernel_launch(void* const* d_in, const int* in_sizes, int n_in,
                              void* d_out, int out_size) {
    const float* x     = (const float*)d_in[0];
    const float* Win   = (const float*)d_in[1];
    const float* cw    = (const float*)d_in[2];
    const float* cb    = (const float*)d_in[3];
    const float* Wx    = (const float*)d_in[4];
    const float* Wdt   = (const float*)d_in[5];
    const float* bdt   = (const float*)d_in[6];
    const float* Alogs = (const float*)d_in[7];
    const float* Ds    = (const float*)d_in[8];
    const float* Wout  = (const float*)d_in[9];
    float* out = (float*)d_out;

    dim3 gg(BB * LL / 64, 6);
    k_in_gemm<<<gg, 256>>>(x, Win);
    k_conv<<<(BB * LL * (DI / 4) + 255) / 256, 256>>>(cw, cb);
    dim3 gp(LL / 64, 2, BB);
    k_proj<<<gp, 160>>>(Wx, Wdt, bdt);
    dim3 gs(DI / 4, 8, BB);              // y = dir*2 + chunk
    k_scan<<<gs, 32>>>(Alogs, Ds);
    dim3 go(BB * LL / 64, 3);
    k_out<<<go, 128>>>(Wout, out);
}

// round 5
// speedup vs baseline: 2.3265x; 1.0899x over previous
#include <cuda_runtime.h>

#define BB 4
#define HH 64
#define WW 64
#define LL 4096
#define DM 96
#define DI 192
#define DS 16
#define DR 6
#define NPROJ 38
#define CH 1024            // scan chunk length (4 chunks)
#define DXPAD 16           // float2 pad around g_dx (prefetch overrun)
#define BCPAD 64           // float4 pad around g_bc (prefetch overrun)

// ---------------- scratch ----------------
__device__ __align__(16) float  g_xcraw[BB * LL * DI];
__device__ __align__(16) float  g_siluz[BB * LL * DI];
__device__ __align__(16) float  g_xca  [BB * LL * DI];
__device__ __align__(16) float2 g_dx_raw[DXPAD + BB * 2 * DI * LL + DXPAD];
__device__ __align__(16) float4 g_bc_raw[BCPAD + BB * 2 * LL * 8 + BCPAD];
__device__ __align__(16) float  g_ysum [BB * LL * DI];

__device__ __forceinline__ float silu_f(float v) {
    return v * __frcp_rn(1.f + __expf(-v));
}
__device__ __forceinline__ float ex2f(float x) {
    float y; asm("ex2.approx.ftz.f32 %0, %1;" : "=f"(y) : "f"(x)); return y;
}

// ---------------- kernel 1: xz = x @ W_in (64x64 tile, 4x4 microtile) ----------------
__global__ void k_in_gemm(const float* __restrict__ x, const float* __restrict__ Win) {
    __shared__ __align__(16) float xs[64][96];
    __shared__ __align__(16) float ws[96][64];
    const int t = threadIdx.x;                   // 256
    const int row0 = blockIdx.x * 64;
    const int col0 = blockIdx.y * 64;

    {
        const float4* xg = (const float4*)(x + (size_t)row0 * DM);
        float4* xv = (float4*)&xs[0][0];
        #pragma unroll
        for (int i = 0; i < 6; i++) xv[t + i * 256] = xg[t + i * 256];
    }
    {
        #pragma unroll
        for (int i = 0; i < 6; i++) {
            const int idx = t + i * 256;
            const int k = idx >> 4, c4 = idx & 15;
            *(float4*)&ws[k][c4 * 4] = *(const float4*)&Win[k * (2 * DI) + col0 + c4 * 4];
        }
    }
    __syncthreads();

    const int tx = t & 15, ty = t >> 4;
    float acc[4][4];
    #pragma unroll
    for (int i = 0; i < 4; i++)
        #pragma unroll
        for (int jj = 0; jj < 4; jj++) acc[i][jj] = 0.f;

    #pragma unroll 8
    for (int kk = 0; kk < 96; kk++) {
        const float4 bv = *(const float4*)&ws[kk][tx * 4];
        const float a0 = xs[ty * 4 + 0][kk];
        const float a1 = xs[ty * 4 + 1][kk];
        const float a2 = xs[ty * 4 + 2][kk];
        const float a3 = xs[ty * 4 + 3][kk];
        acc[0][0] += a0 * bv.x; acc[0][1] += a0 * bv.y; acc[0][2] += a0 * bv.z; acc[0][3] += a0 * bv.w;
        acc[1][0] += a1 * bv.x; acc[1][1] += a1 * bv.y; acc[1][2] += a1 * bv.z; acc[1][3] += a1 * bv.w;
        acc[2][0] += a2 * bv.x; acc[2][1] += a2 * bv.y; acc[2][2] += a2 * bv.z; acc[2][3] += a2 * bv.w;
        acc[3][0] += a3 * bv.x; acc[3][1] += a3 * bv.y; acc[3][2] += a3 * bv.z; acc[3][3] += a3 * bv.w;
    }

    if (col0 < DI) {
        #pragma unroll
        for (int i = 0; i < 4; i++) {
            const int row = row0 + ty * 4 + i;
            *(float4*)&g_xcraw[(size_t)row * DI + col0 + tx * 4] =
                make_float4(acc[i][0], acc[i][1], acc[i][2], acc[i][3]);
        }
    } else {
        const int c = col0 - DI;
        #pragma unroll
        for (int i = 0; i < 4; i++) {
            const int row = row0 + ty * 4 + i;
            *(float4*)&g_siluz[(size_t)row * DI + c + tx * 4] =
                make_float4(silu_f(acc[i][0]), silu_f(acc[i][1]),
                            silu_f(acc[i][2]), silu_f(acc[i][3]));
        }
    }
}

// ---------------- kernel 2: depthwise 3x3 conv + bias + SiLU ----------------
__global__ void k_conv(const float* __restrict__ cw, const float* __restrict__ cb) {
    const int idx = blockIdx.x * blockDim.x + threadIdx.x;
    if (idx >= BB * LL * (DI / 4)) return;
    const int cv = idx % (DI / 4);
    const int c  = cv * 4;
    const int l  = (idx / (DI / 4)) % LL;
    const int b  = idx / (LL * (DI / 4));
    const int h = l >> 6, w = l & 63;

    float4 acc = make_float4(0.f, 0.f, 0.f, 0.f);
    #pragma unroll
    for (int kh = 0; kh < 3; kh++) {
        const int hh = h + kh - 1;
        if (hh < 0 || hh >= HH) continue;
        #pragma unroll
        for (int kw = 0; kw < 3; kw++) {
            const int wv = w + kw - 1;
            if (wv < 0 || wv >= WW) continue;
            const float4 v  = *(const float4*)&g_xcraw[((size_t)(b * LL) + (hh * WW + wv)) * DI + c];
            const float4 wt = *(const float4*)&cw[(kh * 3 + kw) * DI + c];
            acc.x += v.x * wt.x; acc.y += v.y * wt.y;
            acc.z += v.z * wt.z; acc.w += v.w * wt.w;
        }
    }
    const float4 bv = *(const float4*)&cb[c];
    float4 o;
    o.x = silu_f(acc.x + bv.x);
    o.y = silu_f(acc.y + bv.y);
    o.z = silu_f(acc.z + bv.z);
    o.w = silu_f(acc.w + bv.w);
    *(float4*)&g_xca[((size_t)(b * LL) + l) * DI + c] = o;
}

// ---------------- kernel 3: x-proj + delta + ysum D-init ----------------
__global__ __launch_bounds__(160) void k_proj(const float* __restrict__ Wx,
                                              const float* __restrict__ Wdt,
                                              const float* __restrict__ bdt,
                                              const float* __restrict__ Dsg) {
    __shared__ __align__(16) float xs[64][33];
    __shared__ __align__(16) float ws[32][40];
    __shared__ float xdbl[64][41];
    __shared__ float wdt_s[DR][DI];
    __shared__ float bdt_s[DI];
    __shared__ float dsum_s[DI];
    const int t  = threadIdx.x;                   // 160
    const int p0 = blockIdx.x * 64;
    const int m  = blockIdx.y;
    const int b  = blockIdx.z;
    const int tx = t % 10, ty = t / 10;

    // preload small weights
    for (int i = t; i < DR * DI; i += 160) ((float*)wdt_s)[i] = Wdt[i];
    for (int i = t; i < DI; i += 160) {
        bdt_s[i]  = bdt[i];
        dsum_s[i] = Dsg[i] + Dsg[DI + i] + Dsg[2 * DI + i] + Dsg[3 * DI + i];
    }
    __syncthreads();

    // ysum init = xca * sum_k Ds[k]  (m=0 blocks; exact for all 4 directions)
    if (m == 0) {
        for (int i = t; i < 64 * DI; i += 160) {
            const int r = i / DI, c = i % DI;
            const size_t gi = ((size_t)b * LL + p0 + r) * DI + c;
            g_ysum[gi] = g_xca[gi] * dsum_s[c];
        }
    }

    float acc[4][4];
    #pragma unroll
    for (int i = 0; i < 4; i++)
        #pragma unroll
        for (int q = 0; q < 4; q++) acc[i][q] = 0.f;

    // phase A: xdbl[64][38] = rows @ Wx, K-tiled by 32
    for (int kt = 0; kt < 6; kt++) {
        __syncthreads();
        for (int i = t; i < 64 * 32; i += 160) {
            const int r = i >> 5, c = i & 31;
            const int p = p0 + r;
            const int src = m ? (((p & 63) << 6) | (p >> 6)) : p;
            xs[r][c] = g_xca[((size_t)b * LL + src) * DI + kt * 32 + c];
        }
        for (int i = t; i < 32 * 40; i += 160) {
            const int k = i / 40, j = i % 40;
            ws[k][j] = (j < NPROJ) ? Wx[(kt * 32 + k) * NPROJ + j] : 0.f;
        }
        __syncthreads();

        #pragma unroll 8
        for (int kk = 0; kk < 32; kk++) {
            const float4 bv = *(const float4*)&ws[kk][tx * 4];
            const float a0 = xs[ty * 4 + 0][kk];
            const float a1 = xs[ty * 4 + 1][kk];
            const float a2 = xs[ty * 4 + 2][kk];
            const float a3 = xs[ty * 4 + 3][kk];
            acc[0][0] += a0 * bv.x; acc[0][1] += a0 * bv.y; acc[0][2] += a0 * bv.z; acc[0][3] += a0 * bv.w;
            acc[1][0] += a1 * bv.x; acc[1][1] += a1 * bv.y; acc[1][2] += a1 * bv.z; acc[1][3] += a1 * bv.w;
            acc[2][0] += a2 * bv.x; acc[2][1] += a2 * bv.y; acc[2][2] += a2 * bv.z; acc[2][3] += a2 * bv.w;
            acc[3][0] += a3 * bv.x; acc[3][1] += a3 * bv.y; acc[3][2] += a3 * bv.z; acc[3][3] += a3 * bv.w;
        }
    }
    #pragma unroll
    for (int i = 0; i < 4; i++)
        #pragma unroll
        for (int q = 0; q < 4; q++)
            xdbl[ty * 4 + i][tx * 4 + q] = acc[i][q];
    __syncthreads();

    // BC write: packed (Bj,Cj | Bj+8,Cj+8), position-major
    {
        float2* bc2 = (float2*)(g_bc_raw + BCPAD);
        for (int i = t; i < 64 * 16; i += 160) {
            const int pi = i >> 4, n = i & 15;
            bc2[(((size_t)(b * 2 + m) * LL + p0 + pi) * 8 + (n & 7)) * 2 + (n >> 3)] =
                make_float2(xdbl[pi][DR + n], xdbl[pi][DR + DS + n]);
        }
    }

    // phase B: delta + dx write, d-tiled by 32
    float2* dxw = g_dx_raw + DXPAD;
    for (int dt = 0; dt < 6; dt++) {
        __syncthreads();
        for (int i = t; i < 64 * 32; i += 160) {
            const int r = i >> 5, c = i & 31;
            const int p = p0 + r;
            const int src = m ? (((p & 63) << 6) | (p >> 6)) : p;
            xs[r][c] = g_xca[((size_t)b * LL + src) * DI + dt * 32 + c];
        }
        __syncthreads();
        for (int i = t; i < 32 * 64; i += 160) {
            const int dl = i >> 6, pi = i & 63;
            const int d = dt * 32 + dl;
            float v = bdt_s[d];
            #pragma unroll
            for (int r = 0; r < DR; r++) v += xdbl[pi][r] * wdt_s[r][d];
            const float sp = (v > 20.f) ? v : log1pf(__expf(v));
            dxw[((size_t)((b * 2 + m) * DI + d)) * LL + p0 + pi] =
                make_float2(sp, xs[pi][dl]);
        }
    }
}

// ---------------- kernel 4: selective scan (4 chunks, dual-slot pipeline) ----------------
#define LOADG(S, pd_, pb_)                                             \
    S##_dxa = (pd_)[0]; S##_dxb = (pd_)[1];                            \
    S##_c0 = (pb_)[0];  S##_c1 = (pb_)[8];                             \
    S##_c2 = (pb_)[16]; S##_c3 = (pb_)[24];

#define STEPL(del, xv, bcv) {                                          \
    const float dA0 = ex2f((del) * A0);                                \
    const float dA1 = ex2f((del) * A1);                                \
    const float tv = (del) * (xv);                                     \
    h0 = fmaf(dA0, h0, tv * (bcv).x);                                  \
    h1 = fmaf(dA1, h1, tv * (bcv).z); }

#define STEPE(del, xv, bcv, yidx) {                                    \
    const float dA0 = ex2f((del) * A0);                                \
    const float dA1 = ex2f((del) * A1);                                \
    const float tv = (del) * (xv);                                     \
    h0 = fmaf(dA0, h0, tv * (bcv).x);                                  \
    h1 = fmaf(dA1, h1, tv * (bcv).z);                                  \
    float y = fmaf(h1, (bcv).w, h0 * (bcv).y);                         \
    y += __shfl_xor_sync(0xffffffffu, y, 1);                           \
    y += __shfl_xor_sync(0xffffffffu, y, 2);                           \
    y += __shfl_xor_sync(0xffffffffu, y, 4);                           \
    if (j == 0) atomicAdd(ysu + (yidx), y); }

#define TBASE(sp) ((size_t)(m ? (((sp & 63) << 6) | (sp >> 6)) : (sp)) * DI)

#define GBF_E(S, sp) { const size_t tb = TBASE(sp);                    \
    STEPE(S##_dxa.x, S##_dxa.y, S##_c0, tb);                           \
    STEPE(S##_dxa.z, S##_dxa.w, S##_c1, tb + stm);                     \
    STEPE(S##_dxb.x, S##_dxb.y, S##_c2, tb + 2 * stm);                 \
    STEPE(S##_dxb.z, S##_dxb.w, S##_c3, tb + 3 * stm); }

#define GBF_L(S) {                                                     \
    STEPL(S##_dxa.x, S##_dxa.y, S##_c0);                               \
    STEPL(S##_dxa.z, S##_dxa.w, S##_c1);                               \
    STEPL(S##_dxb.x, S##_dxb.y, S##_c2);                               \
    STEPL(S##_dxb.z, S##_dxb.w, S##_c3); }

#define GBR_E(S, sp) { const size_t tb = TBASE(sp);                    \
    STEPE(S##_dxb.z, S##_dxb.w, S##_c3, tb + 3 * stm);                 \
    STEPE(S##_dxb.x, S##_dxb.y, S##_c2, tb + 2 * stm);                 \
    STEPE(S##_dxa.z, S##_dxa.w, S##_c1, tb + stm);                     \
    STEPE(S##_dxa.x, S##_dxa.y, S##_c0, tb); }

#define GBR_L(S) {                                                     \
    STEPL(S##_dxb.z, S##_dxb.w, S##_c3);                               \
    STEPL(S##_dxb.x, S##_dxb.y, S##_c2);                               \
    STEPL(S##_dxa.z, S##_dxa.w, S##_c1);                               \
    STEPL(S##_dxa.x, S##_dxa.y, S##_c0); }

#define WALKF(lo, hi, EMIT) {                                          \
    float4 s0_dxa, s0_dxb, s0_c0, s0_c1, s0_c2, s0_c3;                 \
    float4 s1_dxa, s1_dxb, s1_c0, s1_c1, s1_c2, s1_c3;                 \
    const float4* pd = (const float4*)(dxr + (lo));                    \
    const float4* pb = bcr + (size_t)(lo) * 8;                         \
    LOADG(s0, pd, pb);                                                 \
    LOADG(s1, pd + 2, pb + 32);                                        \
    const float4* pdn = pd + 4;                                        \
    const float4* pbn = pb + 64;                                       \
    int sp = (lo);                                                     \
    for (int it = ((hi) - (lo)) >> 3; it > 0; it--) {                  \
        if (EMIT) { GBF_E(s0, sp); } else { GBF_L(s0); }               \
        LOADG(s0, pdn, pbn);                                           \
        if (EMIT) { GBF_E(s1, (sp + 4)); } else { GBF_L(s1); }         \
        LOADG(s1, pdn + 2, pbn + 32);                                  \
        pdn += 4; pbn += 64; sp += 8;                                  \
    } }

#define WALKR(lo, hi, EMIT) {                                          \
    float4 s0_dxa, s0_dxb, s0_c0, s0_c1, s0_c2, s0_c3;                 \
    float4 s1_dxa, s1_dxb, s1_c0, s1_c1, s1_c2, s1_c3;                 \
    const float4* pd = (const float4*)(dxr + (hi) - 4);                \
    const float4* pb = bcr + (size_t)((hi) - 4) * 8;                   \
    LOADG(s0, pd, pb);                                                 \
    LOADG(s1, pd - 2, pb - 32);                                        \
    const float4* pdn = pd - 4;                                        \
    const float4* pbn = pb - 64;                                       \
    int sp = (hi) - 4;                                                 \
    for (int it = ((hi) - (lo)) >> 3; it > 0; it--) {                  \
        if (EMIT) { GBR_E(s0, sp); } else { GBR_L(s0); }               \
        LOADG(s0, pdn, pbn);                                           \
        if (EMIT) { GBR_E(s1, (sp - 4)); } else { GBR_L(s1); }         \
        LOADG(s1, pdn - 2, pbn - 32);                                  \
        pdn -= 4; pbn -= 64; sp -= 8;                                  \
    } }

__global__ __launch_bounds__(32) void k_scan(const float* __restrict__ A_logs) {
    const int k  = blockIdx.y >> 2;            // direction 0..3
    const int ch = blockIdx.y & 3;             // chunk 0..3 (scan order)
    const int b  = blockIdx.z;
    const int d  = blockIdx.x * 4 + (threadIdx.x >> 3);
    const int j  = threadIdx.x & 7;
    const int m = k >> 1, rev = k & 1;
    const float L2E = 1.4426950408889634f;

    const float A0 = -__expf(__ldg(&A_logs[(k * DI + d) * DS + j]))     * L2E;
    const float A1 = -__expf(__ldg(&A_logs[(k * DI + d) * DS + j + 8])) * L2E;

    const float2* dxr = g_dx_raw + DXPAD + (size_t)((b * 2 + m) * DI + d) * LL;
    const float4* bcr = g_bc_raw + BCPAD + (size_t)(b * 2 + m) * LL * 8 + j;
    float* ysu = g_ysum + (size_t)b * LL * DI + d;
    const size_t stm = (size_t)(m ? 64 : 1) * DI;

    float h0 = 0.f, h1 = 0.f;

    if (!rev) {
        if (ch) WALKF(0, ch * CH, 0);
        WALKF(ch * CH, (ch + 1) * CH, 1);
    } else {
        if (ch) WALKR(LL - ch * CH, LL, 0);
        WALKR(LL - (ch + 1) * CH, LL - ch * CH, 1);
    }
}

// ---------------- kernel 5: out = (ysum * siluz) @ W_out ----------------
__global__ void k_out(const float* __restrict__ Wout, float* __restrict__ out) {
    __shared__ __align__(16) float ins[64][96];
    __shared__ __align__(16) float ws[96][32];
    const int t = threadIdx.x;                    // 128
    const int row0 = blockIdx.x * 64;
    const int col0 = blockIdx.y * 32;
    const int tx = t & 7, ty = t >> 3;

    float acc[4][4];
    #pragma unroll
    for (int i = 0; i < 4; i++)
        #pragma unroll
        for (int jj = 0; jj < 4; jj++) acc[i][jj] = 0.f;

    for (int kc = 0; kc < 2; kc++) {
        __syncthreads();
        #pragma unroll
        for (int i = 0; i < 12; i++) {
            const int idx = t + i * 128;
            const int r = idx / 24, k4 = idx % 24;
            const size_t gi = (size_t)(row0 + r) * DI + kc * 96 + k4 * 4;
            const float4 a = *(const float4*)&g_ysum[gi];
            const float4 z = *(const float4*)&g_siluz[gi];
            *(float4*)&ins[r][k4 * 4] = make_float4(a.x * z.x, a.y * z.y, a.z * z.z, a.w * z.w);
        }
        #pragma unroll
        for (int i = 0; i < 6; i++) {
            const int idx = t + i * 128;
            const int kk = idx / 8, c4 = idx % 8;
            *(float4*)&ws[kk][c4 * 4] = *(const float4*)&Wout[(kc * 96 + kk) * DM + col0 + c4 * 4];
        }
        __syncthreads();

        #pragma unroll 8
        for (int kk = 0; kk < 96; kk++) {
            const float4 bv = *(const float4*)&ws[kk][tx * 4];
            const float a0 = ins[ty * 4 + 0][kk];
            const float a1 = ins[ty * 4 + 1][kk];
            const float a2 = ins[ty * 4 + 2][kk];
            const float a3 = ins[ty * 4 + 3][kk];
            acc[0][0] += a0 * bv.x; acc[0][1] += a0 * bv.y; acc[0][2] += a0 * bv.z; acc[0][3] += a0 * bv.w;
            acc[1][0] += a1 * bv.x; acc[1][1] += a1 * bv.y; acc[1][2] += a1 * bv.z; acc[1][3] += a1 * bv.w;
            acc[2][0] += a2 * bv.x; acc[2][1] += a2 * bv.y; acc[2][2] += a2 * bv.z; acc[2][3] += a2 * bv.w;
            acc[3][0] += a3 * bv.x; acc[3][1] += a3 * bv.y; acc[3][2] += a3 * bv.z; acc[3][3] += a3 * bv.w;
        }
    }

    #pragma unroll
    for (int i = 0; i < 4; i++) {
        const int row = row0 + ty * 4 + i;
        *(float4*)&out[(size_t)row * DM + col0 + tx * 4] =
            make_float4(acc[i][0], acc[i][1], acc[i][2], acc[i][3]);
    }
}

// ---------------- launch ----------------
extern "C" void kernel_launch(void* const* d_in, const int* in_sizes, int n_in,
                              void* d_out, int out_size) {
    const float* x     = (const float*)d_in[0];
    const float* Win   = (const float*)d_in[1];
    const float* cw    = (const float*)d_in[2];
    const float* cb    = (const float*)d_in[3];
    const float* Wx    = (const float*)d_in[4];
    const float* Wdt   = (const float*)d_in[5];
    const float* bdt   = (const float*)d_in[6];
    const float* Alogs = (const float*)d_in[7];
    const float* Ds    = (const float*)d_in[8];
    const float* Wout  = (const float*)d_in[9];
    float* out = (float*)d_out;

    dim3 gg(BB * LL / 64, 6);
    k_in_gemm<<<gg, 256>>>(x, Win);
    k_conv<<<(BB * LL * (DI / 4) + 255) / 256, 256>>>(cw, cb);
    dim3 gp(LL / 64, 2, BB);
    k_proj<<<gp, 160>>>(Wx, Wdt, bdt, Ds);
    dim3 gs(DI / 4, 16, BB);             // y = dir*4 + chunk
    k_scan<<<gs, 32>>>(Alogs);
    dim3 go(BB * LL / 64, 3);
    k_out<<<go, 128>>>(Wout, out);
}

// round 7
// speedup vs baseline: 3.0155x; 1.2962x over previous
#include <cuda_runtime.h>

#define BB 4
#define HH 64
#define WW 64
#define LL 4096
#define DM 96
#define DI 192
#define DS 16
#define DR 6
#define NPROJ 38
#define CHN 8              // number of scan chunks
#define CH2 512            // chunk length = LL/CHN
#define DXPAD 16           // float2 pad around g_dx (prefetch overrun)
#define BCPAD 64           // float4 pad around g_bc (prefetch overrun)

// ---------------- scratch ----------------
__device__ __align__(16) float  g_xcraw[BB * LL * DI];
__device__ __align__(16) float  g_siluz[BB * LL * DI];
__device__ __align__(16) float  g_xca  [BB * LL * DI];
__device__ __align__(16) float2 g_dx_raw[DXPAD + BB * 2 * DI * LL + DXPAD];
__device__ __align__(16) float4 g_bc_raw[BCPAD + BB * 2 * LL * 8 + BCPAD];
__device__ __align__(16) float  g_ysum [BB * LL * DI];
__device__ __align__(16) float  g_h    [BB * 4 * CHN * DI * 16];  // chunk summaries -> incoming states
__device__ __align__(16) float  g_sd   [BB * 4 * CHN * DI];       // per-chunk delta sums

__device__ __forceinline__ float silu_f(float v) {
    return v * __frcp_rn(1.f + __expf(-v));
}
__device__ __forceinline__ float ex2f(float x) {
    float y; asm("ex2.approx.ftz.f32 %0, %1;" : "=f"(y) : "f"(x)); return y;
}

// ---------------- kernel 1: xz = x @ W_in (64x64 tile, 4x4 microtile) ----------------
__global__ void k_in_gemm(const float* __restrict__ x, const float* __restrict__ Win) {
    __shared__ __align__(16) float xs[64][96];
    __shared__ __align__(16) float ws[96][64];
    const int t = threadIdx.x;                   // 256
    const int row0 = blockIdx.x * 64;
    const int col0 = blockIdx.y * 64;

    {
        const float4* xg = (const float4*)(x + (size_t)row0 * DM);
        float4* xv = (float4*)&xs[0][0];
        #pragma unroll
        for (int i = 0; i < 6; i++) xv[t + i * 256] = xg[t + i * 256];
    }
    {
        #pragma unroll
        for (int i = 0; i < 6; i++) {
            const int idx = t + i * 256;
            const int k = idx >> 4, c4 = idx & 15;
            *(float4*)&ws[k][c4 * 4] = *(const float4*)&Win[k * (2 * DI) + col0 + c4 * 4];
        }
    }
    __syncthreads();

    const int tx = t & 15, ty = t >> 4;
    float acc[4][4];
    #pragma unroll
    for (int i = 0; i < 4; i++)
        #pragma unroll
        for (int jj = 0; jj < 4; jj++) acc[i][jj] = 0.f;

    #pragma unroll 8
    for (int kk = 0; kk < 96; kk++) {
        const float4 bv = *(const float4*)&ws[kk][tx * 4];
        const float a0 = xs[ty * 4 + 0][kk];
        const float a1 = xs[ty * 4 + 1][kk];
        const float a2 = xs[ty * 4 + 2][kk];
        const float a3 = xs[ty * 4 + 3][kk];
        acc[0][0] += a0 * bv.x; acc[0][1] += a0 * bv.y; acc[0][2] += a0 * bv.z; acc[0][3] += a0 * bv.w;
        acc[1][0] += a1 * bv.x; acc[1][1] += a1 * bv.y; acc[1][2] += a1 * bv.z; acc[1][3] += a1 * bv.w;
        acc[2][0] += a2 * bv.x; acc[2][1] += a2 * bv.y; acc[2][2] += a2 * bv.z; acc[2][3] += a2 * bv.w;
        acc[3][0] += a3 * bv.x; acc[3][1] += a3 * bv.y; acc[3][2] += a3 * bv.z; acc[3][3] += a3 * bv.w;
    }

    if (col0 < DI) {
        #pragma unroll
        for (int i = 0; i < 4; i++) {
            const int row = row0 + ty * 4 + i;
            *(float4*)&g_xcraw[(size_t)row * DI + col0 + tx * 4] =
                make_float4(acc[i][0], acc[i][1], acc[i][2], acc[i][3]);
        }
    } else {
        const int c = col0 - DI;
        #pragma unroll
        for (int i = 0; i < 4; i++) {
            const int row = row0 + ty * 4 + i;
            *(float4*)&g_siluz[(size_t)row * DI + c + tx * 4] =
                make_float4(silu_f(acc[i][0]), silu_f(acc[i][1]),
                            silu_f(acc[i][2]), silu_f(acc[i][3]));
        }
    }
}

// ---------------- kernel 2: depthwise 3x3 conv + bias + SiLU ----------------
__global__ void k_conv(const float* __restrict__ cw, const float* __restrict__ cb) {
    const int idx = blockIdx.x * blockDim.x + threadIdx.x;
    if (idx >= BB * LL * (DI / 4)) return;
    const int cv = idx % (DI / 4);
    const int c  = cv * 4;
    const int l  = (idx / (DI / 4)) % LL;
    const int b  = idx / (LL * (DI / 4));
    const int h = l >> 6, w = l & 63;

    float4 acc = make_float4(0.f, 0.f, 0.f, 0.f);
    #pragma unroll
    for (int kh = 0; kh < 3; kh++) {
        const int hh = h + kh - 1;
        if (hh < 0 || hh >= HH) continue;
        #pragma unroll
        for (int kw = 0; kw < 3; kw++) {
            const int wv = w + kw - 1;
            if (wv < 0 || wv >= WW) continue;
            const float4 v  = *(const float4*)&g_xcraw[((size_t)(b * LL) + (hh * WW + wv)) * DI + c];
            const float4 wt = *(const float4*)&cw[(kh * 3 + kw) * DI + c];
            acc.x += v.x * wt.x; acc.y += v.y * wt.y;
            acc.z += v.z * wt.z; acc.w += v.w * wt.w;
        }
    }
    const float4 bv = *(const float4*)&cb[c];
    float4 o;
    o.x = silu_f(acc.x + bv.x);
    o.y = silu_f(acc.y + bv.y);
    o.z = silu_f(acc.z + bv.z);
    o.w = silu_f(acc.w + bv.w);
    *(float4*)&g_xca[((size_t)(b * LL) + l) * DI + c] = o;
}

// ---------------- kernel 3: x-proj + delta + ysum D-init ----------------
__global__ __launch_bounds__(160) void k_proj(const float* __restrict__ Wx,
                                              const float* __restrict__ Wdt,
                                              const float* __restrict__ bdt,
                                              const float* __restrict__ Dsg) {
    __shared__ __align__(16) float xs[64][33];
    __shared__ __align__(16) float ws[32][40];
    __shared__ float xdbl[64][41];
    __shared__ float wdt_s[DR][DI];
    __shared__ float bdt_s[DI];
    __shared__ float dsum_s[DI];
    const int t  = threadIdx.x;                   // 160
    const int p0 = blockIdx.x * 64;
    const int m  = blockIdx.y;
    const int b  = blockIdx.z;
    const int tx = t % 10, ty = t / 10;

    for (int i = t; i < DR * DI; i += 160) ((float*)wdt_s)[i] = Wdt[i];
    for (int i = t; i < DI; i += 160) {
        bdt_s[i]  = bdt[i];
        dsum_s[i] = Dsg[i] + Dsg[DI + i] + Dsg[2 * DI + i] + Dsg[3 * DI + i];
    }
    __syncthreads();

    if (m == 0) {
        for (int i = t; i < 64 * DI; i += 160) {
            const int r = i / DI, c = i % DI;
            const size_t gi = ((size_t)b * LL + p0 + r) * DI + c;
            g_ysum[gi] = g_xca[gi] * dsum_s[c];
        }
    }

    float acc[4][4];
    #pragma unroll
    for (int i = 0; i < 4; i++)
        #pragma unroll
        for (int q = 0; q < 4; q++) acc[i][q] = 0.f;

    for (int kt = 0; kt < 6; kt++) {
        __syncthreads();
        for (int i = t; i < 64 * 32; i += 160) {
            const int r = i >> 5, c = i & 31;
            const int p = p0 + r;
            const int src = m ? (((p & 63) << 6) | (p >> 6)) : p;
            xs[r][c] = g_xca[((size_t)b * LL + src) * DI + kt * 32 + c];
        }
        for (int i = t; i < 32 * 40; i += 160) {
            const int k = i / 40, j = i % 40;
            ws[k][j] = (j < NPROJ) ? Wx[(kt * 32 + k) * NPROJ + j] : 0.f;
        }
        __syncthreads();

        #pragma unroll 8
        for (int kk = 0; kk < 32; kk++) {
            const float4 bv = *(const float4*)&ws[kk][tx * 4];
            const float a0 = xs[ty * 4 + 0][kk];
            const float a1 = xs[ty * 4 + 1][kk];
            const float a2 = xs[ty * 4 + 2][kk];
            const float a3 = xs[ty * 4 + 3][kk];
            acc[0][0] += a0 * bv.x; acc[0][1] += a0 * bv.y; acc[0][2] += a0 * bv.z; acc[0][3] += a0 * bv.w;
            acc[1][0] += a1 * bv.x; acc[1][1] += a1 * bv.y; acc[1][2] += a1 * bv.z; acc[1][3] += a1 * bv.w;
            acc[2][0] += a2 * bv.x; acc[2][1] += a2 * bv.y; acc[2][2] += a2 * bv.z; acc[2][3] += a2 * bv.w;
            acc[3][0] += a3 * bv.x; acc[3][1] += a3 * bv.y; acc[3][2] += a3 * bv.z; acc[3][3] += a3 * bv.w;
        }
    }
    #pragma unroll
    for (int i = 0; i < 4; i++)
        #pragma unroll
        for (int q = 0; q < 4; q++)
            xdbl[ty * 4 + i][tx * 4 + q] = acc[i][q];
    __syncthreads();

    {
        float2* bc2 = (float2*)(g_bc_raw + BCPAD);
        for (int i = t; i < 64 * 16; i += 160) {
            const int pi = i >> 4, n = i & 15;
            bc2[(((size_t)(b * 2 + m) * LL + p0 + pi) * 8 + (n & 7)) * 2 + (n >> 3)] =
                make_float2(xdbl[pi][DR + n], xdbl[pi][DR + DS + n]);
        }
    }

    float2* dxw = g_dx_raw + DXPAD;
    for (int dt = 0; dt < 6; dt++) {
        __syncthreads();
        for (int i = t; i < 64 * 32; i += 160) {
            const int r = i >> 5, c = i & 31;
            const int p = p0 + r;
            const int src = m ? (((p & 63) << 6) | (p >> 6)) : p;
            xs[r][c] = g_xca[((size_t)b * LL + src) * DI + dt * 32 + c];
        }
        __syncthreads();
        for (int i = t; i < 32 * 64; i += 160) {
            const int dl = i >> 6, pi = i & 63;
            const int d = dt * 32 + dl;
            float v = bdt_s[d];
            #pragma unroll
            for (int r = 0; r < DR; r++) v += xdbl[pi][r] * wdt_s[r][d];
            const float sp = (v > 20.f) ? v : log1pf(__expf(v));
            dxw[((size_t)((b * 2 + m) * DI + d)) * LL + p0 + pi] =
                make_float2(sp, xs[pi][dl]);
        }
    }
}

// ---------------- scan macros ----------------
#define LOADG(S, pd_, pb_)                                             \
    S##_dxa = (pd_)[0]; S##_dxb = (pd_)[1];                            \
    S##_c0 = (pb_)[0];  S##_c1 = (pb_)[8];                             \
    S##_c2 = (pb_)[16]; S##_c3 = (pb_)[24];

// light step: state + delta-sum only
#define STEPQ(del, xv, bcv) {                                          \
    const float dA0 = ex2f((del) * A0);                                \
    const float dA1 = ex2f((del) * A1);                                \
    const float tv = (del) * (xv);                                     \
    h0 = fmaf(dA0, h0, tv * (bcv).x);                                  \
    h1 = fmaf(dA1, h1, tv * (bcv).z);                                  \
    sd += (del); }

// emit step
#define STEPE(del, xv, bcv, yidx) {                                    \
    const float dA0 = ex2f((del) * A0);                                \
    const float dA1 = ex2f((del) * A1);                                \
    const float tv = (del) * (xv);                                     \
    h0 = fmaf(dA0, h0, tv * (bcv).x);                                  \
    h1 = fmaf(dA1, h1, tv * (bcv).z);                                  \
    float y = fmaf(h1, (bcv).w, h0 * (bcv).y);                         \
    y += __shfl_xor_sync(0xffffffffu, y, 1);                           \
    y += __shfl_xor_sync(0xffffffffu, y, 2);                           \
    y += __shfl_xor_sync(0xffffffffu, y, 4);                           \
    if (j == 0) atomicAdd(ysu + (yidx), y); }

#define TBASE(sp) ((size_t)(m ? (((sp & 63) << 6) | (sp >> 6)) : (sp)) * DI)

// all group macros take (S, sp); light variants ignore sp
#define GBQ_F(S, sp) {                                                 \
    STEPQ(S##_dxa.x, S##_dxa.y, S##_c0);                               \
    STEPQ(S##_dxa.z, S##_dxa.w, S##_c1);                               \
    STEPQ(S##_dxb.x, S##_dxb.y, S##_c2);                               \
    STEPQ(S##_dxb.z, S##_dxb.w, S##_c3); }

#define GBQ_R(S, sp) {                                                 \
    STEPQ(S##_dxb.z, S##_dxb.w, S##_c3);                               \
    STEPQ(S##_dxb.x, S##_dxb.y, S##_c2);                               \
    STEPQ(S##_dxa.z, S##_dxa.w, S##_c1);                               \
    STEPQ(S##_dxa.x, S##_dxa.y, S##_c0); }

#define GBE_F(S, sp) { const size_t tb = TBASE(sp);                    \
    STEPE(S##_dxa.x, S##_dxa.y, S##_c0, tb);                           \
    STEPE(S##_dxa.z, S##_dxa.w, S##_c1, tb + stm);                     \
    STEPE(S##_dxb.x, S##_dxb.y, S##_c2, tb + 2 * stm);                 \
    STEPE(S##_dxb.z, S##_dxb.w, S##_c3, tb + 3 * stm); }

#define GBE_R(S, sp) { const size_t tb = TBASE(sp);                    \
    STEPE(S##_dxb.z, S##_dxb.w, S##_c3, tb + 3 * stm);                 \
    STEPE(S##_dxb.x, S##_dxb.y, S##_c2, tb + 2 * stm);                 \
    STEPE(S##_dxa.z, S##_dxa.w, S##_c1, tb + stm);                     \
    STEPE(S##_dxa.x, S##_dxa.y, S##_c0, tb); }

#define WALK_F(lo, hi, GB) {                                           \
    float4 s0_dxa, s0_dxb, s0_c0, s0_c1, s0_c2, s0_c3;                 \
    float4 s1_dxa, s1_dxb, s1_c0, s1_c1, s1_c2, s1_c3;                 \
    const float4* pd = (const float4*)(dxr + (lo));                    \
    const float4* pb = bcr + (size_t)(lo) * 8;                         \
    LOADG(s0, pd, pb);                                                 \
    LOADG(s1, pd + 2, pb + 32);                                        \
    const float4* pdn = pd + 4;                                        \
    const float4* pbn = pb + 64;                                       \
    int sp = (lo);                                                     \
    for (int it = ((hi) - (lo)) >> 3; it > 0; it--) {                  \
        GB(s0, sp);                                                    \
        LOADG(s0, pdn, pbn);                                           \
        GB(s1, (sp + 4));                                              \
        LOADG(s1, pdn + 2, pbn + 32);                                  \
        pdn += 4; pbn += 64; sp += 8;                                  \
    } }

#define WALK_R(lo, hi, GB) {                                           \
    float4 s0_dxa, s0_dxb, s0_c0, s0_c1, s0_c2, s0_c3;                 \
    float4 s1_dxa, s1_dxb, s1_c0, s1_c1, s1_c2, s1_c3;                 \
    const float4* pd = (const float4*)(dxr + (hi) - 4);                \
    const float4* pb = bcr + (size_t)((hi) - 4) * 8;                   \
    LOADG(s0, pd, pb);                                                 \
    LOADG(s1, pd - 2, pb - 32);                                        \
    const float4* pdn = pd - 4;                                        \
    const float4* pbn = pb - 64;                                       \
    int sp = (hi) - 4;                                                 \
    for (int it = ((hi) - (lo)) >> 3; it > 0; it--) {                  \
        GB(s0, sp);                                                    \
        LOADG(s0, pdn, pbn);                                           \
        GB(s1, (sp - 4));                                              \
        LOADG(s1, pdn - 2, pbn - 32);                                  \
        pdn -= 4; pbn -= 64; sp -= 8;                                  \
    } }

// ---------------- kernel 4a: phase-1 chunk summaries ----------------
__global__ __launch_bounds__(32) void k_scan1(const float* __restrict__ A_logs) {
    const int k  = blockIdx.y >> 3;            // direction 0..3
    const int ch = blockIdx.y & 7;             // chunk in scan order
    const int b  = blockIdx.z;
    const int d  = blockIdx.x * 4 + (threadIdx.x >> 3);
    const int j  = threadIdx.x & 7;
    const int m = k >> 1, rev = k & 1;
    const float L2E = 1.4426950408889634f;

    const float A0 = -__expf(__ldg(&A_logs[(k * DI + d) * DS + j]))     * L2E;
    const float A1 = -__expf(__ldg(&A_logs[(k * DI + d) * DS + j + 8])) * L2E;

    const float2* dxr = g_dx_raw + DXPAD + (size_t)((b * 2 + m) * DI + d) * LL;
    const float4* bcr = g_bc_raw + BCPAD + (size_t)(b * 2 + m) * LL * 8 + j;

    float h0 = 0.f, h1 = 0.f, sd = 0.f;

    if (!rev) { WALK_F(ch * CH2, (ch + 1) * CH2, GBQ_F); }
    else      { WALK_R(LL - (ch + 1) * CH2, LL - ch * CH2, GBQ_R); }

    const int base = (((b * 4 + k) * CHN + ch) * DI + d) * 16;
    g_h[base + j]     = h0;
    g_h[base + j + 8] = h1;
    if (j == 0) g_sd[((b * 4 + k) * CHN + ch) * DI + d] = sd;
}

// ---------------- kernel 4b: chunk-prefix combine ----------------
__global__ void k_comb(const float* __restrict__ A_logs) {
    const int idx = blockIdx.x * blockDim.x + threadIdx.x;
    if (idx >= BB * 4 * DI * 16) return;
    const int n = idx & 15;
    const int d = (idx >> 4) % DI;
    const int k = ((idx >> 4) / DI) & 3;
    const int b2 = idx / (4 * DI * 16);
    const float L2E = 1.4426950408889634f;
    const float A = -__expf(A_logs[(k * DI + d) * DS + n]) * L2E;

    float hin = 0.f;
    #pragma unroll
    for (int c = 0; c < CHN; c++) {
        const int base = (((b2 * 4 + k) * CHN + c) * DI + d) * 16;
        const float hc = g_h[base + n];
        const float P  = ex2f(A * g_sd[((b2 * 4 + k) * CHN + c) * DI + d]);
        g_h[base + n] = hin;                   // overwrite summary with incoming state
        hin = fmaf(P, hin, hc);
    }
}

// ---------------- kernel 4c: phase-3 emit ----------------
__global__ __launch_bounds__(32) void k_scan2(const float* __restrict__ A_logs) {
    const int k  = blockIdx.y >> 3;
    const int ch = blockIdx.y & 7;
    const int b  = blockIdx.z;
    const int d  = blockIdx.x * 4 + (threadIdx.x >> 3);
    const int j  = threadIdx.x & 7;
    const int m = k >> 1, rev = k & 1;
    const float L2E = 1.4426950408889634f;

    const float A0 = -__expf(__ldg(&A_logs[(k * DI + d) * DS + j]))     * L2E;
    const float A1 = -__expf(__ldg(&A_logs[(k * DI + d) * DS + j + 8])) * L2E;

    const float2* dxr = g_dx_raw + DXPAD + (size_t)((b * 2 + m) * DI + d) * LL;
    const float4* bcr = g_bc_raw + BCPAD + (size_t)(b * 2 + m) * LL * 8 + j;
    float* ysu = g_ysum + (size_t)b * LL * DI + d;
    const size_t stm = (size_t)(m ? 64 : 1) * DI;

    const int base = (((b * 4 + k) * CHN + ch) * DI + d) * 16;
    float h0 = g_h[base + j];
    float h1 = g_h[base + j + 8];

    if (!rev) { WALK_F(ch * CH2, (ch + 1) * CH2, GBE_F); }
    else      { WALK_R(LL - (ch + 1) * CH2, LL - ch * CH2, GBE_R); }
}

// ---------------- kernel 5: out = (ysum * siluz) @ W_out ----------------
__global__ void k_out(const float* __restrict__ Wout, float* __restrict__ out) {
    __shared__ __align__(16) float ins[64][96];
    __shared__ __align__(16) float ws[96][32];
    const int t = threadIdx.x;                    // 128
    const int row0 = blockIdx.x * 64;
    const int col0 = blockIdx.y * 32;
    const int tx = t & 7, ty = t >> 3;

    float acc[4][4];
    #pragma unroll
    for (int i = 0; i < 4; i++)
        #pragma unroll
        for (int jj = 0; jj < 4; jj++) acc[i][jj] = 0.f;

    for (int kc = 0; kc < 2; kc++) {
        __syncthreads();
        #pragma unroll
        for (int i = 0; i < 12; i++) {
            const int idx = t + i * 128;
            const int r = idx / 24, k4 = idx % 24;
            const size_t gi = (size_t)(row0 + r) * DI + kc * 96 + k4 * 4;
            const float4 a = *(const float4*)&g_ysum[gi];
            const float4 z = *(const float4*)&g_siluz[gi];
            *(float4*)&ins[r][k4 * 4] = make_float4(a.x * z.x, a.y * z.y, a.z * z.z, a.w * z.w);
        }
        #pragma unroll
        for (int i = 0; i < 6; i++) {
            const int idx = t + i * 128;
            const int kk = idx / 8, c4 = idx % 8;
            *(float4*)&ws[kk][c4 * 4] = *(const float4*)&Wout[(kc * 96 + kk) * DM + col0 + c4 * 4];
        }
        __syncthreads();

        #pragma unroll 8
        for (int kk = 0; kk < 96; kk++) {
            const float4 bv = *(const float4*)&ws[kk][tx * 4];
            const float a0 = ins[ty * 4 + 0][kk];
            const float a1 = ins[ty * 4 + 1][kk];
            const float a2 = ins[ty * 4 + 2][kk];
            const float a3 = ins[ty * 4 + 3][kk];
            acc[0][0] += a0 * bv.x; acc[0][1] += a0 * bv.y; acc[0][2] += a0 * bv.z; acc[0][3] += a0 * bv.w;
            acc[1][0] += a1 * bv.x; acc[1][1] += a1 * bv.y; acc[1][2] += a1 * bv.z; acc[1][3] += a1 * bv.w;
            acc[2][0] += a2 * bv.x; acc[2][1] += a2 * bv.y; acc[2][2] += a2 * bv.z; acc[2][3] += a2 * bv.w;
            acc[3][0] += a3 * bv.x; acc[3][1] += a3 * bv.y; acc[3][2] += a3 * bv.z; acc[3][3] += a3 * bv.w;
        }
    }

    #pragma unroll
    for (int i = 0; i < 4; i++) {
        const int row = row0 + ty * 4 + i;
        *(float4*)&out[(size_t)row * DM + col0 + tx * 4] =
            make_float4(acc[i][0], acc[i][1], acc[i][2], acc[i][3]);
    }
}

// ---------------- launch ----------------
extern "C" void kernel_launch(void* const* d_in, const int* in_sizes, int n_in,
                              void* d_out, int out_size) {
    const float* x     = (const float*)d_in[0];
    const float* Win   = (const float*)d_in[1];
    const float* cw    = (const float*)d_in[2];
    const float* cb    = (const float*)d_in[3];
    const float* Wx    = (const float*)d_in[4];
    const float* Wdt   = (const float*)d_in[5];
    const float* bdt   = (const float*)d_in[6];
    const float* Alogs = (const float*)d_in[7];
    const float* Ds    = (const float*)d_in[8];
    const float* Wout  = (const float*)d_in[9];
    float* out = (float*)d_out;

    dim3 gg(BB * LL / 64, 6);
    k_in_gemm<<<gg, 256>>>(x, Win);
    k_conv<<<(BB * LL * (DI / 4) + 255) / 256, 256>>>(cw, cb);
    dim3 gp(LL / 64, 2, BB);
    k_proj<<<gp, 160>>>(Wx, Wdt, bdt, Ds);
    dim3 gs(DI / 4, 4 * CHN, BB);        // y = dir*8 + chunk
    k_scan1<<<gs, 32>>>(Alogs);
    k_comb<<<(BB * 4 * DI * 16 + 255) / 256, 256>>>(Alogs);
    k_scan2<<<gs, 32>>>(Alogs);
    dim3 go(BB * LL / 64, 3);
    k_out<<<go, 128>>>(Wout, out);
}